// round 3
// baseline (speedup 1.0000x reference)
#include <cuda_runtime.h>

// Problem constants (fixed by setup_inputs):
//   coefficients: [64, 256, 45] f32
//   NOShfS=16, NOShfR=16, NOShfA=8, NOShfZ=8
//   output row = 12*(16+16) + 66*8*8 = 384 + 4224 = 4608 f32
#define NBLK    16384        // 64*256 (n,a) pairs
#define NCOEFF  45
#define ROWLEN  4608

__constant__ int c_src[36] = {
     9, 10, 11, 12, 13, 14, 15, 16, 17, 18, 19, 20,   // p
    21, 23, 26, 25, 24, 22,                            // d group 0
    27, 29, 32, 31, 30, 28,                            // d group 1
    33, 35, 38, 37, 36, 34,                            // d group 2
    39, 41, 44, 43, 42, 40                             // d group 3
};

// triu_indices(12, k=1), i-major (66 pairs)
__constant__ unsigned char c_iu[66] = {
    0,0,0,0,0,0,0,0,0,0,0,
    1,1,1,1,1,1,1,1,1,1,
    2,2,2,2,2,2,2,2,2,
    3,3,3,3,3,3,3,3,
    4,4,4,4,4,4,4,
    5,5,5,5,5,5,
    6,6,6,6,6,
    7,7,7,7,
    8,8,8,
    9,9,
    10
};
__constant__ unsigned char c_ju[66] = {
    1,2,3,4,5,6,7,8,9,10,11,
    2,3,4,5,6,7,8,9,10,11,
    3,4,5,6,7,8,9,10,11,
    4,5,6,7,8,9,10,11,
    5,6,7,8,9,10,11,
    6,7,8,9,10,11,
    7,8,9,10,11,
    8,9,10,11,
    9,10,11,
    10,11,
    11
};

// cos/sin of shfZ[k] = (2k+1)*pi/16  (linspace(pi/16, 15pi/16, 8))
__constant__ float c_cz[8] = {
     0.98078528f,  0.83146961f,  0.55557023f,  0.19509032f,
    -0.19509032f, -0.55557023f, -0.83146961f, -0.98078528f
};
__constant__ float c_sz[8] = {
     0.19509032f,  0.55557023f,  0.83146961f,  0.98078528f,
     0.98078528f,  0.83146961f,  0.55557023f,  0.19509032f
};

__global__ void __launch_bounds__(128, 12)
aev_kernel(const float* __restrict__ coeff, float* __restrict__ out)
{
    const int blk = blockIdx.x;     // flat (n*256 + a)
    const int t   = threadIdx.x;

    __shared__ float s_nv[12][3];
    __shared__ float s_dist[12];
    __shared__ __align__(16) float s_rad[192];   // [12][16]  (s_aev == r_aev)
    __shared__ float s_f1[528];                  // [66][8]  includes the 2x factor
    __shared__ __align__(16) float s_f2[528];    // [66][8]

    // ---- Phase A: orbital vectors, norms, normalized vectors ----
    const float* cp = coeff + (size_t)blk * NCOEFF;
    if (t < 12) {
        float x = __ldg(cp + c_src[t * 3 + 0]);
        float y = __ldg(cp + c_src[t * 3 + 1]);
        float z = __ldg(cp + c_src[t * 3 + 2]);
        float d = sqrtf(fmaf(x, x, fmaf(y, y, z * z)));
        bool zero = (fabsf(x) < 1e-12f) & (fabsf(y) < 1e-12f) & (fabsf(z) < 1e-12f);
        float inv = zero ? 0.0f : 1.0f / d;
        s_nv[t][0] = x * inv;
        s_nv[t][1] = y * inv;
        s_nv[t][2] = z * inv;
        s_dist[t]  = d;
    }
    __syncthreads();

    // ---- Phase B: radial staging: rad[v][s] = exp(-16*(d_v - shf_s)^2), shf = 0.5 + 0.2*s
    #pragma unroll
    for (int i = t; i < 192; i += 128) {
        int v = i >> 4, s = i & 15;
        float diff = s_dist[v] - fmaf((float)s, 0.2f, 0.5f);
        s_rad[i] = __expf(-16.0f * diff * diff);
    }
    __syncthreads();

    float4* orow = reinterpret_cast<float4*>(out + (size_t)blk * ROWLEN);

    // ---- Early radial stores: first 96 float4s (384 floats) depend only on phase B.
    // Default (evict-normal) stores: dirty output lines may stay resident in the
    // 126MB L2 and get overwritten by the next graph replay, eliding DRAM writeback.
    if (t < 96) {
        int elem = t << 2;
        int v = elem >> 5;
        int s = elem & 15;
        float4 val = *reinterpret_cast<const float4*>(&s_rad[v * 16 + s]);
        orow[t] = val;
    }

    // ---- Phase C: per-pair angular factors (threads 0..65) ----
    if (t < 66) {
        int i = c_iu[t], j = c_ju[t];
        float dotv = s_nv[i][0] * s_nv[j][0]
                   + s_nv[i][1] * s_nv[j][1]
                   + s_nv[i][2] * s_nv[j][2];
        float c = 0.95f * dotv;                       // = cos(angle)
        float s = sqrtf(fmaxf(1.0f - c * c, 0.0f));   // = sin(angle), angle in [0,pi]
        float avd = 0.5f * (s_dist[i] + s_dist[j]);
        #pragma unroll
        for (int z = 0; z < 8; z++) {
            // cos(angle - shfZ[z]) = c*cz + s*sz   (no arccos needed)
            float base = 0.5f * (1.0f + fmaf(c, c_cz[z], s * c_sz[z]));
            float p = base * base;   // ^2
            p = p * p;               // ^4
            p = p * p;               // ^8
            p = p * p;               // ^16
            p = p * p;               // ^32
            s_f1[t * 8 + z] = 2.0f * p;
        }
        #pragma unroll
        for (int a = 0; a < 8; a++) {
            float diff = avd - fmaf((float)a, 0.42857143f, 0.5f);  // shfA = 0.5 + 3/7*a
            s_f2[t * 8 + a] = __expf(-8.0f * diff * diff);
        }
    }
    __syncthreads();

    // ---- Phase D: angular region, 1056 float4s, fully coalesced writeback stores.
    // q = float4 index within angular region (0..1055):
    //   element index ae = 4q; pz = ae>>3 = q>>1; pa = (ae>>6)*8 + (ae&7) = (q>>4)*8 + (q&1)*4
    float4* oang = orow + 96;
    int q = t;
    #pragma unroll
    for (int it = 0; it < 8; it++) {
        float  f1 = s_f1[q >> 1];
        float4 f2 = *reinterpret_cast<const float4*>(&s_f2[((q >> 4) << 3) + ((q & 1) << 2)]);
        oang[q] = make_float4(f1 * f2.x, f1 * f2.y, f1 * f2.z, f1 * f2.w);
        q += 128;
    }
    // last partial wave: q = 1024 + t, valid while < 1056  (t < 32)
    if (t < 32) {
        float  f1 = s_f1[q >> 1];
        float4 f2 = *reinterpret_cast<const float4*>(&s_f2[((q >> 4) << 3) + ((q & 1) << 2)]);
        oang[q] = make_float4(f1 * f2.x, f1 * f2.y, f1 * f2.z, f1 * f2.w);
    }
}

extern "C" void kernel_launch(void* const* d_in, const int* in_sizes, int n_in,
                              void* d_out, int out_size)
{
    const float* coeff = (const float*)d_in[0];
    float* out = (float*)d_out;
    aev_kernel<<<NBLK, 128>>>(coeff, out);
}

// round 4
// speedup vs baseline: 1.0200x; 1.0200x over previous
#include <cuda_runtime.h>

// Problem constants (fixed by setup_inputs):
//   coefficients: [64, 256, 45] f32
//   NOShfS=16, NOShfR=16, NOShfA=8, NOShfZ=8
//   output row = 12*(16+16) + 66*8*8 = 384 + 4224 = 4608 f32
#define NBLK    16384        // 64*256 (n,a) pairs
#define NCOEFF  45
#define ROWLEN  4608
#define GRIDSZ  2048         // persistent CTAs; each handles 8 rows, stride GRIDSZ
#define ITERS   8            // NBLK / GRIDSZ

__constant__ int c_src[36] = {
     9, 10, 11, 12, 13, 14, 15, 16, 17, 18, 19, 20,   // p
    21, 23, 26, 25, 24, 22,                            // d group 0
    27, 29, 32, 31, 30, 28,                            // d group 1
    33, 35, 38, 37, 36, 34,                            // d group 2
    39, 41, 44, 43, 42, 40                             // d group 3
};

// triu_indices(12, k=1), i-major (66 pairs)
__constant__ unsigned char c_iu[66] = {
    0,0,0,0,0,0,0,0,0,0,0,
    1,1,1,1,1,1,1,1,1,1,
    2,2,2,2,2,2,2,2,2,
    3,3,3,3,3,3,3,3,
    4,4,4,4,4,4,4,
    5,5,5,5,5,5,
    6,6,6,6,6,
    7,7,7,7,
    8,8,8,
    9,9,
    10
};
__constant__ unsigned char c_ju[66] = {
    1,2,3,4,5,6,7,8,9,10,11,
    2,3,4,5,6,7,8,9,10,11,
    3,4,5,6,7,8,9,10,11,
    4,5,6,7,8,9,10,11,
    5,6,7,8,9,10,11,
    6,7,8,9,10,11,
    7,8,9,10,11,
    8,9,10,11,
    9,10,11,
    10,11,
    11
};

// cos/sin of shfZ[k] = (2k+1)*pi/16  (linspace(pi/16, 15pi/16, 8))
__constant__ float c_cz[8] = {
     0.98078528f,  0.83146961f,  0.55557023f,  0.19509032f,
    -0.19509032f, -0.55557023f, -0.83146961f, -0.98078528f
};
__constant__ float c_sz[8] = {
     0.19509032f,  0.55557023f,  0.83146961f,  0.98078528f,
     0.98078528f,  0.83146961f,  0.55557023f,  0.19509032f
};

// Compute all per-row staged factors for row `blk` into the given buffers.
// Contains ONE internal __syncthreads (A -> B/C dependency on s_dist/s_nv).
// Caller must place a barrier before the buffers are consumed.
__device__ __forceinline__ void compute_block(
    const float* __restrict__ coeff, int blk, int t,
    float (*s_nv)[3], float* s_dist,
    float* s_rad, float* s_f1, float* s_f2)
{
    const float* cp = coeff + (size_t)blk * NCOEFF;
    if (t < 12) {
        float x = __ldg(cp + c_src[t * 3 + 0]);
        float y = __ldg(cp + c_src[t * 3 + 1]);
        float z = __ldg(cp + c_src[t * 3 + 2]);
        float d = sqrtf(fmaf(x, x, fmaf(y, y, z * z)));
        bool zero = (fabsf(x) < 1e-12f) & (fabsf(y) < 1e-12f) & (fabsf(z) < 1e-12f);
        float inv = zero ? 0.0f : 1.0f / d;
        s_nv[t][0] = x * inv;
        s_nv[t][1] = y * inv;
        s_nv[t][2] = z * inv;
        s_dist[t]  = d;
    }
    __syncthreads();

    // radial: rad[v][s] = exp(-16*(d_v - shf_s)^2), shf = 0.5 + 0.2*s
    #pragma unroll
    for (int i = t; i < 192; i += 128) {
        int v = i >> 4, s = i & 15;
        float diff = s_dist[v] - fmaf((float)s, 0.2f, 0.5f);
        s_rad[i] = __expf(-16.0f * diff * diff);
    }

    // angular pair factors (threads 0..65)
    if (t < 66) {
        int i = c_iu[t], j = c_ju[t];
        float dotv = s_nv[i][0] * s_nv[j][0]
                   + s_nv[i][1] * s_nv[j][1]
                   + s_nv[i][2] * s_nv[j][2];
        float c = 0.95f * dotv;                       // = cos(angle)
        float s = sqrtf(fmaxf(1.0f - c * c, 0.0f));   // = sin(angle)
        float avd = 0.5f * (s_dist[i] + s_dist[j]);
        #pragma unroll
        for (int z = 0; z < 8; z++) {
            // cos(angle - shfZ[z]) = c*cz + s*sz   (no arccos needed)
            float base = 0.5f * (1.0f + fmaf(c, c_cz[z], s * c_sz[z]));
            float p = base * base;   // ^2
            p = p * p;               // ^4
            p = p * p;               // ^8
            p = p * p;               // ^16
            p = p * p;               // ^32
            s_f1[t * 8 + z] = 2.0f * p;
        }
        #pragma unroll
        for (int a = 0; a < 8; a++) {
            float diff = avd - fmaf((float)a, 0.42857143f, 0.5f);  // shfA = 0.5 + 3/7*a
            s_f2[t * 8 + a] = __expf(-8.0f * diff * diff);
        }
    }
}

// Stream the 4608-float row (1152 float4, 9 per thread), fully coalesced, evict-first.
__device__ __forceinline__ void store_block(
    float* __restrict__ out, int blk, int t,
    const float* s_rad, const float* s_f1, const float* s_f2)
{
    float4* orow = reinterpret_cast<float4*>(out + (size_t)blk * ROWLEN);
    #pragma unroll
    for (int it = 0; it < 9; it++) {
        int e4   = it * 128 + t;   // float4 index, 0..1151
        int elem = e4 << 2;        // float index within row
        float4 val;
        if (elem < 384) {
            // radial: v = elem/32, shf index = elem%16 (s_aev duplicated as r_aev)
            int v = elem >> 5;
            int s = elem & 15;
            val = *reinterpret_cast<const float4*>(&s_rad[v * 16 + s]);
        } else {
            int ae  = elem - 384;                   // 0..4223
            int pz  = ae >> 3;                      // pair*8 + z
            int pa  = ((ae >> 6) << 3) + (ae & 7);  // pair*8 + a (a in {0,4})
            float  f1 = s_f1[pz];
            float4 f2 = *reinterpret_cast<const float4*>(&s_f2[pa]);
            val = make_float4(f1 * f2.x, f1 * f2.y, f1 * f2.z, f1 * f2.w);
        }
        __stcs(&orow[e4], val);
    }
}

__global__ void __launch_bounds__(128, 8)
aev_kernel(const float* __restrict__ coeff, float* __restrict__ out)
{
    const int t = threadIdx.x;

    __shared__ float s_nv[2][12][3];
    __shared__ float s_dist[2][12];
    __shared__ __align__(16) float s_rad[2][192];
    __shared__ float s_f1[2][528];
    __shared__ __align__(16) float s_f2[2][528];

    // Prologue: fill buffer 0 with row blockIdx.x
    compute_block(coeff, blockIdx.x, t, s_nv[0], s_dist[0], s_rad[0], s_f1[0], s_f2[0]);
    __syncthreads();

    // Pipelined main loop: store row i from buf (i&1) while computing row i+1
    // into the other buffer. Stores are fire-and-forget; the closing barrier
    // protects buffer reuse two iterations later.
    #pragma unroll 1
    for (int i = 0; i < ITERS; i++) {
        int cur = i & 1;
        store_block(out, blockIdx.x + i * GRIDSZ, t,
                    s_rad[cur], s_f1[cur], s_f2[cur]);
        if (i < ITERS - 1) {
            int nxt = cur ^ 1;
            compute_block(coeff, blockIdx.x + (i + 1) * GRIDSZ, t,
                          s_nv[nxt], s_dist[nxt], s_rad[nxt], s_f1[nxt], s_f2[nxt]);
        }
        __syncthreads();
    }
}

extern "C" void kernel_launch(void* const* d_in, const int* in_sizes, int n_in,
                              void* d_out, int out_size)
{
    const float* coeff = (const float*)d_in[0];
    float* out = (float*)d_out;
    aev_kernel<<<GRIDSZ, 128>>>(coeff, out);
}

// round 5
// speedup vs baseline: 1.0213x; 1.0013x over previous
#include <cuda_runtime.h>
#include <cstdint>

// Problem constants (fixed by setup_inputs):
//   coefficients: [64, 256, 45] f32
//   NOShfS=16, NOShfR=16, NOShfA=8, NOShfZ=8
//   output row = 12*(16+16) + 66*8*8 = 384 + 4224 = 4608 f32 = 18432 bytes
#define NBLK     16384
#define NCOEFF   45
#define ROWLEN   4608
#define ROWBYTES 18432

__constant__ int c_src[36] = {
     9, 10, 11, 12, 13, 14, 15, 16, 17, 18, 19, 20,   // p
    21, 23, 26, 25, 24, 22,                            // d group 0
    27, 29, 32, 31, 30, 28,                            // d group 1
    33, 35, 38, 37, 36, 34,                            // d group 2
    39, 41, 44, 43, 42, 40                             // d group 3
};

// triu_indices(12, k=1), i-major (66 pairs)
__constant__ unsigned char c_iu[66] = {
    0,0,0,0,0,0,0,0,0,0,0,
    1,1,1,1,1,1,1,1,1,1,
    2,2,2,2,2,2,2,2,2,
    3,3,3,3,3,3,3,3,
    4,4,4,4,4,4,4,
    5,5,5,5,5,5,
    6,6,6,6,6,
    7,7,7,7,
    8,8,8,
    9,9,
    10
};
__constant__ unsigned char c_ju[66] = {
    1,2,3,4,5,6,7,8,9,10,11,
    2,3,4,5,6,7,8,9,10,11,
    3,4,5,6,7,8,9,10,11,
    4,5,6,7,8,9,10,11,
    5,6,7,8,9,10,11,
    6,7,8,9,10,11,
    7,8,9,10,11,
    8,9,10,11,
    9,10,11,
    10,11,
    11
};

// cos/sin of shfZ[k] = (2k+1)*pi/16
__constant__ float c_cz[8] = {
     0.98078528f,  0.83146961f,  0.55557023f,  0.19509032f,
    -0.19509032f, -0.55557023f, -0.83146961f, -0.98078528f
};
__constant__ float c_sz[8] = {
     0.19509032f,  0.55557023f,  0.83146961f,  0.98078528f,
     0.98078528f,  0.83146961f,  0.55557023f,  0.19509032f
};

__global__ void __launch_bounds__(128, 8)
aev_kernel(const float* __restrict__ coeff, float* __restrict__ out)
{
    const int blk = blockIdx.x;
    const int t   = threadIdx.x;

    __shared__ __align__(128) float s_stage[ROWLEN];  // full output row (18432 B)
    __shared__ float s_nv[12][3];
    __shared__ float s_dist[12];
    __shared__ float s_f1[528];                        // [66][8], includes 2x
    __shared__ __align__(16) float s_f2[528];          // [66][8]

    // ---- Phase A: orbital vectors, norms, normalized vectors ----
    const float* cp = coeff + (size_t)blk * NCOEFF;
    if (t < 12) {
        float x = __ldg(cp + c_src[t * 3 + 0]);
        float y = __ldg(cp + c_src[t * 3 + 1]);
        float z = __ldg(cp + c_src[t * 3 + 2]);
        float d = sqrtf(fmaf(x, x, fmaf(y, y, z * z)));
        bool zero = (fabsf(x) < 1e-12f) & (fabsf(y) < 1e-12f) & (fabsf(z) < 1e-12f);
        float inv = zero ? 0.0f : 1.0f / d;
        s_nv[t][0] = x * inv;
        s_nv[t][1] = y * inv;
        s_nv[t][2] = z * inv;
        s_dist[t]  = d;
    }
    __syncthreads();

    // ---- Phase B: radial values written straight into staging, duplicated
    // (s_aev == r_aev since shfS==shfR and etaS==etaR).
    // staging row layout: [v][32] with [v][0:16]=s_aev, [v][16:32]=r_aev.
    #pragma unroll
    for (int i = t; i < 192; i += 128) {
        int v = i >> 4, s = i & 15;
        float diff = s_dist[v] - fmaf((float)s, 0.2f, 0.5f);
        float e = __expf(-16.0f * diff * diff);
        s_stage[(v << 5) + s]      = e;
        s_stage[(v << 5) + 16 + s] = e;
    }

    // ---- Phase C: per-pair angular factors (threads 0..65) ----
    if (t < 66) {
        int i = c_iu[t], j = c_ju[t];
        float dotv = s_nv[i][0] * s_nv[j][0]
                   + s_nv[i][1] * s_nv[j][1]
                   + s_nv[i][2] * s_nv[j][2];
        float c = 0.95f * dotv;                       // = cos(angle)
        float s = sqrtf(fmaxf(1.0f - c * c, 0.0f));   // = sin(angle), angle in [0,pi]
        float avd = 0.5f * (s_dist[i] + s_dist[j]);
        #pragma unroll
        for (int z = 0; z < 8; z++) {
            // cos(angle - shfZ[z]) = c*cz + s*sz   (arccos eliminated)
            float base = 0.5f * (1.0f + fmaf(c, c_cz[z], s * c_sz[z]));
            float p = base * base;   // ^2
            p = p * p;               // ^4
            p = p * p;               // ^8
            p = p * p;               // ^16
            p = p * p;               // ^32
            s_f1[t * 8 + z] = 2.0f * p;
        }
        #pragma unroll
        for (int a = 0; a < 8; a++) {
            float diff = avd - fmaf((float)a, 0.42857143f, 0.5f);  // shfA = 0.5 + 3/7*a
            s_f2[t * 8 + a] = __expf(-8.0f * diff * diff);
        }
    }
    __syncthreads();

    // ---- Phase D: expand angular outer product into staging (1056 float4s).
    // q = float4 index within angular region; element ae = 4q;
    // pz = q>>1; pa = (q>>4)*8 + (q&1)*4
    float4* stage4 = reinterpret_cast<float4*>(s_stage) + 96;
    int q = t;
    #pragma unroll
    for (int it = 0; it < 8; it++) {
        float  f1 = s_f1[q >> 1];
        float4 f2 = *reinterpret_cast<const float4*>(&s_f2[((q >> 4) << 3) + ((q & 1) << 2)]);
        stage4[q] = make_float4(f1 * f2.x, f1 * f2.y, f1 * f2.z, f1 * f2.w);
        q += 128;
    }
    if (t < 32) {  // q = 1024 + t < 1056
        float  f1 = s_f1[q >> 1];
        float4 f2 = *reinterpret_cast<const float4*>(&s_f2[((q >> 4) << 3) + ((q & 1) << 2)]);
        stage4[q] = make_float4(f1 * f2.x, f1 * f2.y, f1 * f2.z, f1 * f2.w);
    }
    __syncthreads();

    // ---- Phase E: one TMA bulk store drains the whole row SMEM -> GMEM.
    // No per-thread STG traffic through L1tex; no warp issue slots consumed
    // during the drain.
    asm volatile("fence.proxy.async.shared::cta;" ::: "memory");
    if (t == 0) {
        uint32_t saddr;
        asm("{ .reg .u64 x; cvta.to.shared.u64 x, %1; cvt.u32.u64 %0, x; }"
            : "=r"(saddr) : "l"((const void*)s_stage));
        const float* gdst = out + (size_t)blk * ROWLEN;
        asm volatile(
            "cp.async.bulk.global.shared::cta.bulk_group [%0], [%1], %2;"
            :: "l"(gdst), "r"(saddr), "n"(ROWBYTES) : "memory");
        asm volatile("cp.async.bulk.commit_group;" ::: "memory");
        // Wait only until the SMEM reads are done (SMEM may then be freed);
        // the global writes complete asynchronously before kernel end.
        asm volatile("cp.async.bulk.wait_group.read 0;" ::: "memory");
    }
    __syncthreads();
}

extern "C" void kernel_launch(void* const* d_in, const int* in_sizes, int n_in,
                              void* d_out, int out_size)
{
    const float* coeff = (const float*)d_in[0];
    float* out = (float*)d_out;
    aev_kernel<<<NBLK, 128>>>(coeff, out);
}